// round 14
// baseline (speedup 1.0000x reference)
#include <cuda_runtime.h>
#include <cuda_fp16.h>
#include <cstdint>

#define BATCH 8
#define CCH   64
#define DQ    8
#define NPIX  4096
#define TM    32          // m-rows per CTA (2 warps x 16)
#define TN    128
#define NT    (NPIX / TN)
#define L2E   1.4426950408889634f

__device__ __half g_q16[BATCH * NPIX * DQ];                 // pre-scaled by log2(e)
__device__ __half g_k16[BATCH * NPIX * DQ];
__device__ float  g_qn[BATCH * NPIX];
__device__ __half g_v16[(size_t)BATCH * CCH * NPIX];        // [b][c][n]
__device__ float  g_kmax_part[BATCH * 32];

__device__ __forceinline__ uint32_t s2u(const void* p) {
    uint32_t a;
    asm("{ .reg .u64 t; cvta.to.shared.u64 t, %1; cvt.u32.u64 %0, t; }" : "=r"(a) : "l"(p));
    return a;
}
#define CP16(dst, src) asm volatile("cp.async.cg.shared.global [%0], [%1], 16;" :: "r"(dst), "l"(src) : "memory")
#define CPCOMMIT()     asm volatile("cp.async.commit_group;" ::: "memory")
#define CPWAIT1()      asm volatile("cp.async.wait_group 1;" ::: "memory")
#define CPWAIT0()      asm volatile("cp.async.wait_group 0;" ::: "memory")

// ---------------------------------------------------------------------------
// QKV projection (128 thr, grid (32, B)). q,k scalar f32 (+norms);
// V projection on tensor cores (f16 HMMA), bias via C-init.
// ---------------------------------------------------------------------------
#define XS 72

__global__ __launch_bounds__(128) void qkv_kernel(
    const float* __restrict__ x,
    const float* __restrict__ wq, const float* __restrict__ bq,
    const float* __restrict__ wk, const float* __restrict__ bk,
    const float* __restrict__ wv, const float* __restrict__ bv)
{
    __shared__ float swq[DQ * CCH], swk[DQ * CCH];
    __shared__ float sbq[DQ], sbk[DQ], sbv[CCH];
    __shared__ float swmax[4];
    __shared__ __align__(16) __half wv16[CCH][XS];
    __shared__ __align__(16) __half xs[128][XS];

    const int tid = threadIdx.x;
    const int w    = tid >> 5;
    const int lane = tid & 31;
    const int g    = lane >> 2;
    const int c    = lane & 3;
    const int b = blockIdx.y;
    const int n0 = blockIdx.x * 128;

    for (int i = tid; i < DQ * CCH; i += 128) { swq[i] = wq[i]; swk[i] = wk[i]; }
    for (int i = tid; i < CCH * CCH; i += 128) {
        wv16[i >> 6][i & 63] = __float2half_rn(wv[i]);
    }
    if (tid < DQ) { sbq[tid] = bq[tid]; sbk[tid] = bk[tid]; }
    if (tid < CCH) sbv[tid] = bv[tid];

    const int n = n0 + tid;
    float xv[CCH];
    const float* xb = x + ((size_t)b * CCH) * NPIX + n;
    #pragma unroll
    for (int ch = 0; ch < CCH; ch++) xv[ch] = xb[(size_t)ch * NPIX];

    #pragma unroll
    for (int ch = 0; ch < CCH; ch += 2) {
        __half2 h = __floats2half2_rn(xv[ch], xv[ch + 1]);
        *(__half2*)&xs[tid][ch] = h;
    }
    __syncthreads();

    float qv[DQ], kv[DQ];
    #pragma unroll
    for (int d = 0; d < DQ; d++) {
        float aq = sbq[d], ak = sbk[d];
        #pragma unroll
        for (int ch = 0; ch < CCH; ch++) {
            aq = fmaf(swq[d * CCH + ch], xv[ch], aq);
            ak = fmaf(swk[d * CCH + ch], xv[ch], ak);
        }
        qv[d] = aq; kv[d] = ak;
    }
    {
        __half2* qo = (__half2*)&g_q16[((size_t)b * NPIX + n) * DQ];
        __half2* ko = (__half2*)&g_k16[((size_t)b * NPIX + n) * DQ];
        #pragma unroll
        for (int d = 0; d < 4; d++) {
            qo[d] = __floats2half2_rn(qv[2*d] * L2E, qv[2*d+1] * L2E);
            ko[d] = __floats2half2_rn(kv[2*d], kv[2*d+1]);
        }
    }
    {
        float nq2 = 0.f, nk2 = 0.f;
        #pragma unroll
        for (int d = 0; d < DQ; d++) {
            nq2 = fmaf(qv[d], qv[d], nq2);
            nk2 = fmaf(kv[d], kv[d], nk2);
        }
        g_qn[b * NPIX + n] = sqrtf(nq2);
        float nk = sqrtf(nk2);
        #pragma unroll
        for (int off = 16; off > 0; off >>= 1)
            nk = fmaxf(nk, __shfl_xor_sync(0xFFFFFFFFu, nk, off));
        if (lane == 0) swmax[w] = nk;
    }
    __syncthreads();
    if (tid == 0)
        g_kmax_part[b * 32 + blockIdx.x] =
            fmaxf(fmaxf(swmax[0], swmax[1]), fmaxf(swmax[2], swmax[3]));

    // ---- V projection: per warp 32 pixels, m16n8k16 f16 HMMA ----
    uint32_t bf[4][4][2];
    #pragma unroll
    for (int ni = 0; ni < 4; ni++) {
        #pragma unroll
        for (int kp = 0; kp < 2; kp++) {
            const int row = w * 32 + ni * 8 + (lane & 7);
            const int col = kp * 32 + (lane >> 3) * 8;
            uint32_t addr = s2u(&xs[row][col]);
            uint32_t r0, r1, r2, r3;
            asm volatile("ldmatrix.sync.aligned.m8n8.x4.shared.b16 {%0,%1,%2,%3}, [%4];"
                : "=r"(r0), "=r"(r1), "=r"(r2), "=r"(r3) : "r"(addr));
            bf[ni][2*kp][0]   = r0; bf[ni][2*kp][1]   = r1;
            bf[ni][2*kp+1][0] = r2; bf[ni][2*kp+1][1] = r3;
        }
    }
    #pragma unroll
    for (int mi = 0; mi < 4; mi++) {
        uint32_t af[4][4];
        #pragma unroll
        for (int ki = 0; ki < 4; ki++) {
            const int row = mi * 16 + (((lane >> 3) & 1) << 3) + (lane & 7);
            const int col = ki * 16 + ((lane >> 4) << 3);
            uint32_t addr = s2u(&wv16[row][col]);
            asm volatile("ldmatrix.sync.aligned.m8n8.x4.shared.b16 {%0,%1,%2,%3}, [%4];"
                : "=r"(af[ki][0]), "=r"(af[ki][1]), "=r"(af[ki][2]), "=r"(af[ki][3]) : "r"(addr));
        }
        __half2 c0h = __float2half2_rn(sbv[mi * 16 + g]);
        __half2 c1h = __float2half2_rn(sbv[mi * 16 + 8 + g]);
        const uint32_t c0 = *(uint32_t*)&c0h, c1 = *(uint32_t*)&c1h;
        #pragma unroll
        for (int ni = 0; ni < 4; ni++) {
            uint32_t d0 = c0, d1 = c1;
            #pragma unroll
            for (int ki = 0; ki < 4; ki++) {
                asm volatile(
                    "mma.sync.aligned.m16n8k16.row.col.f16.f16.f16.f16 "
                    "{%0,%1},{%2,%3,%4,%5},{%6,%7},{%0,%1};"
                    : "+r"(d0), "+r"(d1)
                    : "r"(af[ki][0]), "r"(af[ki][1]), "r"(af[ki][2]), "r"(af[ki][3]),
                      "r"(bf[ni][ki][0]), "r"(bf[ni][ki][1]));
            }
            const int px = n0 + w * 32 + ni * 8 + 2 * c;
            const int r0 = mi * 16 + g;
            *(uint32_t*)&g_v16[((size_t)(b * CCH + r0))     * NPIX + px] = d0;
            *(uint32_t*)&g_v16[((size_t)(b * CCH + r0 + 8)) * NPIX + px] = d1;
        }
    }
}

// ---------------------------------------------------------------------------
// Flash attention, 64 thr / 2 warps, each warp 16 m-rows (TM=32).
// W=1024 CTAs kills the wave-quantization penalty (ceil(W/148)/avg -> 1.01).
// f16-acc HMMA + per-tile f32 promotion; scalar lsum. Grid (128, 8).
// ---------------------------------------------------------------------------
#define VSTRIDE 136
#define STAGE(t, buf) do { \
    const __half* _ks = g_k16 + ((size_t)b * NPIX + (t) * TN + tid) * DQ; \
    CP16(s2u(&sK[buf][tid][0]), _ks); \
    CP16(s2u(&sK[buf][tid + 64][0]), _ks + 64 * DQ); \
    _Pragma("unroll") \
    for (int _i = 0; _i < 16; _i++) { \
        int _l = _i * 64 + tid, _row = _l >> 4, _seg = _l & 15; \
        const __half* _vs = g_v16 + ((size_t)(b * CCH + _row)) * NPIX + (t) * TN + _seg * 8; \
        CP16(s2u(&sV[buf][_row][_seg * 8]), _vs); \
    } \
} while (0)

__global__ __launch_bounds__(64, 4) void attn_kernel(
    const float* __restrict__ x,
    const float* __restrict__ gamma,
    float* __restrict__ out)
{
    __shared__ __align__(16) __half sK[2][TN][24];
    __shared__ __align__(16) __half sV[2][CCH][VSTRIDE];

    const int tid  = threadIdx.x;
    const int w    = tid >> 5;
    const int lane = tid & 31;
    const int g    = lane >> 2;
    const int c    = lane & 3;
    const int b    = blockIdx.y;
    const int m0   = blockIdx.x * TM + w * 16;

    float kmax = g_kmax_part[b * 32];
    #pragma unroll
    for (int i = 1; i < 32; i++) kmax = fmaxf(kmax, g_kmax_part[b * 32 + i]);

    uint32_t qa0, qa1;
    uint32_t nshC0, nshC1;
    {
        const int rA = m0 + g, rB = rA + 8;
        qa0 = *(const uint32_t*)&g_q16[((size_t)b * NPIX + rA) * DQ + 2 * c];
        qa1 = *(const uint32_t*)&g_q16[((size_t)b * NPIX + rB) * DQ + 2 * c];
        float nA = -g_qn[b * NPIX + rA] * kmax * L2E;
        float nB = -g_qn[b * NPIX + rB] * kmax * L2E;
        __half2 hA = __floats2half2_rn(nA, nA);
        __half2 hB = __floats2half2_rn(nB, nB);
        nshC0 = *(uint32_t*)&hA;
        nshC1 = *(uint32_t*)&hB;
    }

    float acc32[8][4];
    #pragma unroll
    for (int jc = 0; jc < 8; jc++)
        #pragma unroll
        for (int r = 0; r < 4; r++) acc32[jc][r] = 0.f;
    float ls32[2] = {0.f, 0.f};

    const uint32_t vb0 = s2u(&sV[0][((lane >> 4) << 3) + (lane & 7)][((lane >> 3) & 1) * 8]);

    STAGE(0, 0); CPCOMMIT();

    #pragma unroll 1
    for (int t = 0; t < NT; t++) {
        if (t + 1 < NT) { STAGE(t + 1, (t + 1) & 1); CPCOMMIT(); CPWAIT1(); }
        else            { CPWAIT0(); }
        __syncthreads();
        const __half (*K)[24] = sK[t & 1];
        const uint32_t vbase = vb0 + (uint32_t)((t & 1) * CCH * VSTRIDE * 2);

        uint32_t a16[8][2];
        #pragma unroll
        for (int jc = 0; jc < 8; jc++) { a16[jc][0] = 0u; a16[jc][1] = 0u; }

        #pragma unroll
        for (int kc = 0; kc < 8; kc++) {
            const uint32_t kb0 = *(const uint32_t*)&K[kc * 16 + g][2 * c];
            const uint32_t kb1 = *(const uint32_t*)&K[kc * 16 + 8 + g][2 * c];
            uint32_t pf[4];
            {
                uint32_t d0, d1, d2, d3;
                asm volatile(
                    "mma.sync.aligned.m16n8k8.row.col.f16.f16.f16.f16 "
                    "{%0,%1},{%2,%3},{%4},{%5,%6};"
                    : "=r"(d0), "=r"(d1)
                    : "r"(qa0), "r"(qa1), "r"(kb0), "r"(nshC0), "r"(nshC1));
                asm volatile(
                    "mma.sync.aligned.m16n8k8.row.col.f16.f16.f16.f16 "
                    "{%0,%1},{%2,%3},{%4},{%5,%6};"
                    : "=r"(d2), "=r"(d3)
                    : "r"(qa0), "r"(qa1), "r"(kb1), "r"(nshC0), "r"(nshC1));
                asm("ex2.approx.f16x2 %0, %1;" : "=r"(pf[0]) : "r"(d0));
                asm("ex2.approx.f16x2 %0, %1;" : "=r"(pf[1]) : "r"(d1));
                asm("ex2.approx.f16x2 %0, %1;" : "=r"(pf[2]) : "r"(d2));
                asm("ex2.approx.f16x2 %0, %1;" : "=r"(pf[3]) : "r"(d3));
            }
            {
                __half2 sA = __hadd2(*(__half2*)&pf[0], *(__half2*)&pf[2]);
                __half2 sB = __hadd2(*(__half2*)&pf[1], *(__half2*)&pf[3]);
                float2 fA = __half22float2(sA);
                float2 fB = __half22float2(sB);
                ls32[0] += fA.x + fA.y;
                ls32[1] += fB.x + fB.y;
            }
            #pragma unroll
            for (int jp = 0; jp < 4; jp++) {
                uint32_t b00, b01, b10, b11;
                const uint32_t va = vbase + (uint32_t)(jp * 16 * VSTRIDE * 2 + kc * 32);
                asm volatile("ldmatrix.sync.aligned.m8n8.x4.shared.b16 {%0,%1,%2,%3}, [%4];"
                    : "=r"(b00), "=r"(b01), "=r"(b10), "=r"(b11) : "r"(va));
                asm volatile(
                    "mma.sync.aligned.m16n8k16.row.col.f16.f16.f16.f16 "
                    "{%0,%1},{%2,%3,%4,%5},{%6,%7},{%0,%1};"
                    : "+r"(a16[2*jp][0]), "+r"(a16[2*jp][1])
                    : "r"(pf[0]), "r"(pf[1]), "r"(pf[2]), "r"(pf[3]),
                      "r"(b00), "r"(b01));
                asm volatile(
                    "mma.sync.aligned.m16n8k16.row.col.f16.f16.f16.f16 "
                    "{%0,%1},{%2,%3,%4,%5},{%6,%7},{%0,%1};"
                    : "+r"(a16[2*jp+1][0]), "+r"(a16[2*jp+1][1])
                    : "r"(pf[0]), "r"(pf[1]), "r"(pf[2]), "r"(pf[3]),
                      "r"(b10), "r"(b11));
            }
        }
        #pragma unroll
        for (int jc = 0; jc < 8; jc++) {
            float2 f0 = __half22float2(*(__half2*)&a16[jc][0]);
            float2 f1 = __half22float2(*(__half2*)&a16[jc][1]);
            acc32[jc][0] += f0.x; acc32[jc][1] += f0.y;
            acc32[jc][2] += f1.x; acc32[jc][3] += f1.y;
        }
        __syncthreads();
    }

    #pragma unroll
    for (int i = 0; i < 2; i++) {
        ls32[i] += __shfl_xor_sync(0xFFFFFFFFu, ls32[i], 1);
        ls32[i] += __shfl_xor_sync(0xFFFFFFFFu, ls32[i], 2);
    }

    const float gm = gamma[0];
    const float iA = 1.f / ls32[0], iB = 1.f / ls32[1];
    const int rA = m0 + g, rB = rA + 8;
    const float* xb = x   + (size_t)b * CCH * NPIX;
    float*       ob = out + (size_t)b * CCH * NPIX;
    #pragma unroll
    for (int jc = 0; jc < 8; jc++) {
        const int ch0 = jc * 8 + 2 * c, ch1 = ch0 + 1;
        ob[(size_t)ch0 * NPIX + rA] = fmaf(gm, acc32[jc][0] * iA, xb[(size_t)ch0 * NPIX + rA]);
        ob[(size_t)ch1 * NPIX + rA] = fmaf(gm, acc32[jc][1] * iA, xb[(size_t)ch1 * NPIX + rA]);
        ob[(size_t)ch0 * NPIX + rB] = fmaf(gm, acc32[jc][2] * iB, xb[(size_t)ch0 * NPIX + rB]);
        ob[(size_t)ch1 * NPIX + rB] = fmaf(gm, acc32[jc][3] * iB, xb[(size_t)ch1 * NPIX + rB]);
    }
}

// ---------------------------------------------------------------------------
extern "C" void kernel_launch(void* const* d_in, const int* in_sizes, int n_in,
                              void* d_out, int out_size)
{
    const float* x     = (const float*)d_in[0];
    const float* wq    = (const float*)d_in[1];
    const float* bq    = (const float*)d_in[2];
    const float* wk    = (const float*)d_in[3];
    const float* bk    = (const float*)d_in[4];
    const float* wv    = (const float*)d_in[5];
    const float* bv    = (const float*)d_in[6];
    const float* gamma = (const float*)d_in[7];
    float* out = (float*)d_out;

    dim3 g1(NPIX / 128, BATCH);
    qkv_kernel<<<g1, 128>>>(x, wq, bq, wk, bk, wv, bv);
    dim3 g2(NPIX / TM, BATCH);
    attn_kernel<<<g2, 64>>>(x, gamma, out);
}

// round 15
// speedup vs baseline: 1.3779x; 1.3779x over previous
#include <cuda_runtime.h>
#include <cuda_fp16.h>
#include <cstdint>

#define BATCH 8
#define CCH   64
#define DQ    8
#define NPIX  4096
#define TM    128
#define TN    256
#define NT    (NPIX / TN)
#define L2E   1.4426950408889634f

__device__ __half g_q16[BATCH * NPIX * DQ];                 // pre-scaled by log2(e)
__device__ __half g_k16[BATCH * NPIX * DQ];
__device__ float  g_qn[BATCH * NPIX];
__device__ __half g_v16[(size_t)BATCH * CCH * NPIX];        // [b][c][n]
__device__ float  g_kmax_part[BATCH * 32];

__device__ __forceinline__ uint32_t s2u(const void* p) {
    uint32_t a;
    asm("{ .reg .u64 t; cvta.to.shared.u64 t, %1; cvt.u32.u64 %0, t; }" : "=r"(a) : "l"(p));
    return a;
}
#define CP16(dst, src) asm volatile("cp.async.cg.shared.global [%0], [%1], 16;" :: "r"(dst), "l"(src) : "memory")
#define CPCOMMIT()     asm volatile("cp.async.commit_group;" ::: "memory")
#define CPWAIT1()      asm volatile("cp.async.wait_group 1;" ::: "memory")
#define CPWAIT0()      asm volatile("cp.async.wait_group 0;" ::: "memory")

// ---------------------------------------------------------------------------
// QKV projection (128 thr, grid (32, B)). q,k scalar f32 (+norms);
// V projection on tensor cores (f16 HMMA), bias via C-init. (R13, unchanged)
// ---------------------------------------------------------------------------
#define XS 72

__global__ __launch_bounds__(128) void qkv_kernel(
    const float* __restrict__ x,
    const float* __restrict__ wq, const float* __restrict__ bq,
    const float* __restrict__ wk, const float* __restrict__ bk,
    const float* __restrict__ wv, const float* __restrict__ bv)
{
    __shared__ float swq[DQ * CCH], swk[DQ * CCH];
    __shared__ float sbq[DQ], sbk[DQ], sbv[CCH];
    __shared__ float swmax[4];
    __shared__ __align__(16) __half wv16[CCH][XS];
    __shared__ __align__(16) __half xs[128][XS];

    const int tid = threadIdx.x;
    const int w    = tid >> 5;
    const int lane = tid & 31;
    const int g    = lane >> 2;
    const int c    = lane & 3;
    const int b = blockIdx.y;
    const int n0 = blockIdx.x * 128;

    for (int i = tid; i < DQ * CCH; i += 128) { swq[i] = wq[i]; swk[i] = wk[i]; }
    for (int i = tid; i < CCH * CCH; i += 128) {
        wv16[i >> 6][i & 63] = __float2half_rn(wv[i]);
    }
    if (tid < DQ) { sbq[tid] = bq[tid]; sbk[tid] = bk[tid]; }
    if (tid < CCH) sbv[tid] = bv[tid];

    const int n = n0 + tid;
    float xv[CCH];
    const float* xb = x + ((size_t)b * CCH) * NPIX + n;
    #pragma unroll
    for (int ch = 0; ch < CCH; ch++) xv[ch] = xb[(size_t)ch * NPIX];

    #pragma unroll
    for (int ch = 0; ch < CCH; ch += 2) {
        __half2 h = __floats2half2_rn(xv[ch], xv[ch + 1]);
        *(__half2*)&xs[tid][ch] = h;
    }
    __syncthreads();

    float qv[DQ], kv[DQ];
    #pragma unroll
    for (int d = 0; d < DQ; d++) {
        float aq = sbq[d], ak = sbk[d];
        #pragma unroll
        for (int ch = 0; ch < CCH; ch++) {
            aq = fmaf(swq[d * CCH + ch], xv[ch], aq);
            ak = fmaf(swk[d * CCH + ch], xv[ch], ak);
        }
        qv[d] = aq; kv[d] = ak;
    }
    {
        __half2* qo = (__half2*)&g_q16[((size_t)b * NPIX + n) * DQ];
        __half2* ko = (__half2*)&g_k16[((size_t)b * NPIX + n) * DQ];
        #pragma unroll
        for (int d = 0; d < 4; d++) {
            qo[d] = __floats2half2_rn(qv[2*d] * L2E, qv[2*d+1] * L2E);
            ko[d] = __floats2half2_rn(kv[2*d], kv[2*d+1]);
        }
    }
    {
        float nq2 = 0.f, nk2 = 0.f;
        #pragma unroll
        for (int d = 0; d < DQ; d++) {
            nq2 = fmaf(qv[d], qv[d], nq2);
            nk2 = fmaf(kv[d], kv[d], nk2);
        }
        g_qn[b * NPIX + n] = sqrtf(nq2);
        float nk = sqrtf(nk2);
        #pragma unroll
        for (int off = 16; off > 0; off >>= 1)
            nk = fmaxf(nk, __shfl_xor_sync(0xFFFFFFFFu, nk, off));
        if (lane == 0) swmax[w] = nk;
    }
    __syncthreads();
    if (tid == 0)
        g_kmax_part[b * 32 + blockIdx.x] =
            fmaxf(fmaxf(swmax[0], swmax[1]), fmaxf(swmax[2], swmax[3]));

    uint32_t bf[4][4][2];
    #pragma unroll
    for (int ni = 0; ni < 4; ni++) {
        #pragma unroll
        for (int kp = 0; kp < 2; kp++) {
            const int row = w * 32 + ni * 8 + (lane & 7);
            const int col = kp * 32 + (lane >> 3) * 8;
            uint32_t addr = s2u(&xs[row][col]);
            uint32_t r0, r1, r2, r3;
            asm volatile("ldmatrix.sync.aligned.m8n8.x4.shared.b16 {%0,%1,%2,%3}, [%4];"
                : "=r"(r0), "=r"(r1), "=r"(r2), "=r"(r3) : "r"(addr));
            bf[ni][2*kp][0]   = r0; bf[ni][2*kp][1]   = r1;
            bf[ni][2*kp+1][0] = r2; bf[ni][2*kp+1][1] = r3;
        }
    }
    #pragma unroll
    for (int mi = 0; mi < 4; mi++) {
        uint32_t af[4][4];
        #pragma unroll
        for (int ki = 0; ki < 4; ki++) {
            const int row = mi * 16 + (((lane >> 3) & 1) << 3) + (lane & 7);
            const int col = ki * 16 + ((lane >> 4) << 3);
            uint32_t addr = s2u(&wv16[row][col]);
            asm volatile("ldmatrix.sync.aligned.m8n8.x4.shared.b16 {%0,%1,%2,%3}, [%4];"
                : "=r"(af[ki][0]), "=r"(af[ki][1]), "=r"(af[ki][2]), "=r"(af[ki][3]) : "r"(addr));
        }
        __half2 c0h = __float2half2_rn(sbv[mi * 16 + g]);
        __half2 c1h = __float2half2_rn(sbv[mi * 16 + 8 + g]);
        const uint32_t c0 = *(uint32_t*)&c0h, c1 = *(uint32_t*)&c1h;
        #pragma unroll
        for (int ni = 0; ni < 4; ni++) {
            uint32_t d0 = c0, d1 = c1;
            #pragma unroll
            for (int ki = 0; ki < 4; ki++) {
                asm volatile(
                    "mma.sync.aligned.m16n8k16.row.col.f16.f16.f16.f16 "
                    "{%0,%1},{%2,%3,%4,%5},{%6,%7},{%0,%1};"
                    : "+r"(d0), "+r"(d1)
                    : "r"(af[ki][0]), "r"(af[ki][1]), "r"(af[ki][2]), "r"(af[ki][3]),
                      "r"(bf[ni][ki][0]), "r"(bf[ni][ki][1]));
            }
            const int px = n0 + w * 32 + ni * 8 + 2 * c;
            const int r0 = mi * 16 + g;
            *(uint32_t*)&g_v16[((size_t)(b * CCH + r0))     * NPIX + px] = d0;
            *(uint32_t*)&g_v16[((size_t)(b * CCH + r0 + 8)) * NPIX + px] = d1;
        }
    }
}

// ---------------------------------------------------------------------------
// Flash attention, 256 thr / 8 warps, each warp 16 m-rows, TN=256 (16 tiles:
// half the syncs/K-reloads/promotions of TN=128). f16-acc window + f32
// promotion; lsum via f16 ones-MMA. Grid (32, 8).
// ---------------------------------------------------------------------------
#define VSTRIDE 264   // halves; 528B row stride -> ldmatrix rows 4 banks apart
#define STAGE(t, buf) do { \
    const __half* _ks = g_k16 + ((size_t)b * NPIX + (t) * TN + tid) * DQ; \
    CP16(s2u(&sK[buf][tid][0]), _ks); \
    _Pragma("unroll") \
    for (int _i = 0; _i < 8; _i++) { \
        int _l = _i * 256 + tid, _row = _l >> 5, _seg = _l & 31; \
        const __half* _vs = g_v16 + ((size_t)(b * CCH + _row)) * NPIX + (t) * TN + _seg * 8; \
        CP16(s2u(&sV[buf][_row][_seg * 8]), _vs); \
    } \
} while (0)

__global__ __launch_bounds__(256, 2) void attn_kernel(
    const float* __restrict__ x,
    const float* __restrict__ gamma,
    float* __restrict__ out)
{
    __shared__ __align__(16) __half sK[2][TN][24];
    __shared__ __align__(16) __half sV[2][CCH][VSTRIDE];

    const int tid  = threadIdx.x;
    const int w    = tid >> 5;
    const int lane = tid & 31;
    const int g    = lane >> 2;
    const int c    = lane & 3;
    const int b    = blockIdx.y;
    const int m0   = blockIdx.x * TM + w * 16;

    float kmax = g_kmax_part[b * 32];
    #pragma unroll
    for (int i = 1; i < 32; i++) kmax = fmaxf(kmax, g_kmax_part[b * 32 + i]);

    uint32_t qa0, qa1;
    uint32_t nshC0, nshC1;
    {
        const int rA = m0 + g, rB = rA + 8;
        qa0 = *(const uint32_t*)&g_q16[((size_t)b * NPIX + rA) * DQ + 2 * c];
        qa1 = *(const uint32_t*)&g_q16[((size_t)b * NPIX + rB) * DQ + 2 * c];
        float nA = -g_qn[b * NPIX + rA] * kmax * L2E;
        float nB = -g_qn[b * NPIX + rB] * kmax * L2E;
        __half2 hA = __floats2half2_rn(nA, nA);
        __half2 hB = __floats2half2_rn(nB, nB);
        nshC0 = *(uint32_t*)&hA;
        nshC1 = *(uint32_t*)&hB;
    }

    float acc32[8][4];
    #pragma unroll
    for (int jc = 0; jc < 8; jc++)
        #pragma unroll
        for (int r = 0; r < 4; r++) acc32[jc][r] = 0.f;
    float ls32[2] = {0.f, 0.f};

    const uint32_t vb0 = s2u(&sV[0][((lane >> 4) << 3) + (lane & 7)][((lane >> 3) & 1) * 8]);

    STAGE(0, 0); CPCOMMIT();

    #pragma unroll 1
    for (int t = 0; t < NT; t++) {
        if (t + 1 < NT) { STAGE(t + 1, (t + 1) & 1); CPCOMMIT(); CPWAIT1(); }
        else            { CPWAIT0(); }
        __syncthreads();
        const __half (*K)[24] = sK[t & 1];
        const uint32_t vbase = vb0 + (uint32_t)((t & 1) * CCH * VSTRIDE * 2);

        // f16 window accumulators for this tile (8 jc + ones)
        uint32_t a16[9][2];
        #pragma unroll
        for (int jc = 0; jc < 9; jc++) { a16[jc][0] = 0u; a16[jc][1] = 0u; }

        #pragma unroll
        for (int kc = 0; kc < 16; kc++) {
            const uint32_t kb0 = *(const uint32_t*)&K[kc * 16 + g][2 * c];
            const uint32_t kb1 = *(const uint32_t*)&K[kc * 16 + 8 + g][2 * c];
            uint32_t pf[4];
            {
                uint32_t d0, d1, d2, d3;
                asm volatile(
                    "mma.sync.aligned.m16n8k8.row.col.f16.f16.f16.f16 "
                    "{%0,%1},{%2,%3},{%4},{%5,%6};"
                    : "=r"(d0), "=r"(d1)
                    : "r"(qa0), "r"(qa1), "r"(kb0), "r"(nshC0), "r"(nshC1));
                asm volatile(
                    "mma.sync.aligned.m16n8k8.row.col.f16.f16.f16.f16 "
                    "{%0,%1},{%2,%3},{%4},{%5,%6};"
                    : "=r"(d2), "=r"(d3)
                    : "r"(qa0), "r"(qa1), "r"(kb1), "r"(nshC0), "r"(nshC1));
                asm("ex2.approx.f16x2 %0, %1;" : "=r"(pf[0]) : "r"(d0));
                asm("ex2.approx.f16x2 %0, %1;" : "=r"(pf[1]) : "r"(d1));
                asm("ex2.approx.f16x2 %0, %1;" : "=r"(pf[2]) : "r"(d2));
                asm("ex2.approx.f16x2 %0, %1;" : "=r"(pf[3]) : "r"(d3));
            }
            #pragma unroll
            for (int jp = 0; jp < 4; jp++) {
                uint32_t b00, b01, b10, b11;
                const uint32_t va = vbase + (uint32_t)(jp * 16 * VSTRIDE * 2 + kc * 32);
                asm volatile("ldmatrix.sync.aligned.m8n8.x4.shared.b16 {%0,%1,%2,%3}, [%4];"
                    : "=r"(b00), "=r"(b01), "=r"(b10), "=r"(b11) : "r"(va));
                asm volatile(
                    "mma.sync.aligned.m16n8k16.row.col.f16.f16.f16.f16 "
                    "{%0,%1},{%2,%3,%4,%5},{%6,%7},{%0,%1};"
                    : "+r"(a16[2*jp][0]), "+r"(a16[2*jp][1])
                    : "r"(pf[0]), "r"(pf[1]), "r"(pf[2]), "r"(pf[3]),
                      "r"(b00), "r"(b01));
                asm volatile(
                    "mma.sync.aligned.m16n8k16.row.col.f16.f16.f16.f16 "
                    "{%0,%1},{%2,%3,%4,%5},{%6,%7},{%0,%1};"
                    : "+r"(a16[2*jp+1][0]), "+r"(a16[2*jp+1][1])
                    : "r"(pf[0]), "r"(pf[1]), "r"(pf[2]), "r"(pf[3]),
                      "r"(b10), "r"(b11));
            }
            // lsum via ones-MMA (tensor pipe)
            {
                const uint32_t ones = 0x3C003C00u;
                asm volatile(
                    "mma.sync.aligned.m16n8k16.row.col.f16.f16.f16.f16 "
                    "{%0,%1},{%2,%3,%4,%5},{%6,%7},{%0,%1};"
                    : "+r"(a16[8][0]), "+r"(a16[8][1])
                    : "r"(pf[0]), "r"(pf[1]), "r"(pf[2]), "r"(pf[3]),
                      "r"(ones), "r"(ones));
            }
        }
        // promote tile window into f32
        #pragma unroll
        for (int jc = 0; jc < 8; jc++) {
            float2 f0 = __half22float2(*(__half2*)&a16[jc][0]);
            float2 f1 = __half22float2(*(__half2*)&a16[jc][1]);
            acc32[jc][0] += f0.x; acc32[jc][1] += f0.y;
            acc32[jc][2] += f1.x; acc32[jc][3] += f1.y;
        }
        ls32[0] += __half2float(*(__half*)&a16[8][0]);
        ls32[1] += __half2float(*(__half*)&a16[8][1]);
        __syncthreads();
    }

    const float gm = gamma[0];
    const float iA = 1.f / ls32[0], iB = 1.f / ls32[1];
    const int rA = m0 + g, rB = rA + 8;
    const float* xb = x   + (size_t)b * CCH * NPIX;
    float*       ob = out + (size_t)b * CCH * NPIX;
    #pragma unroll
    for (int jc = 0; jc < 8; jc++) {
        const int ch0 = jc * 8 + 2 * c, ch1 = ch0 + 1;
        ob[(size_t)ch0 * NPIX + rA] = fmaf(gm, acc32[jc][0] * iA, xb[(size_t)ch0 * NPIX + rA]);
        ob[(size_t)ch1 * NPIX + rA] = fmaf(gm, acc32[jc][1] * iA, xb[(size_t)ch1 * NPIX + rA]);
        ob[(size_t)ch0 * NPIX + rB] = fmaf(gm, acc32[jc][2] * iB, xb[(size_t)ch0 * NPIX + rB]);
        ob[(size_t)ch1 * NPIX + rB] = fmaf(gm, acc32[jc][3] * iB, xb[(size_t)ch1 * NPIX + rB]);
    }
}

// ---------------------------------------------------------------------------
extern "C" void kernel_launch(void* const* d_in, const int* in_sizes, int n_in,
                              void* d_out, int out_size)
{
    const float* x     = (const float*)d_in[0];
    const float* wq    = (const float*)d_in[1];
    const float* bq    = (const float*)d_in[2];
    const float* wk    = (const float*)d_in[3];
    const float* bk    = (const float*)d_in[4];
    const float* wv    = (const float*)d_in[5];
    const float* bv    = (const float*)d_in[6];
    const float* gamma = (const float*)d_in[7];
    float* out = (float*)d_out;

    dim3 g1(NPIX / 128, BATCH);
    qkv_kernel<<<g1, 128>>>(x, wq, bq, wk, bk, wv, bv);
    dim3 g2(NPIX / TM, BATCH);
    attn_kernel<<<g2, 256>>>(x, gamma, out);
}

// round 16
// speedup vs baseline: 1.3785x; 1.0004x over previous
#include <cuda_runtime.h>
#include <cuda_fp16.h>
#include <cstdint>

#define BATCH 8
#define CCH   64
#define DQ    8
#define NPIX  4096
#define TM    128
#define TN    256
#define NT    (NPIX / TN)
#define L2E   1.4426950408889634f

__device__ __half g_q16[BATCH * NPIX * DQ];                 // pre-scaled by log2(e)
__device__ __half g_k16[BATCH * NPIX * DQ];
__device__ float  g_qn[BATCH * NPIX];
__device__ __half g_v16[(size_t)BATCH * CCH * NPIX];        // [b][c][n]
__device__ float  g_kmax_part[BATCH * 32];

__device__ __forceinline__ uint32_t s2u(const void* p) {
    uint32_t a;
    asm("{ .reg .u64 t; cvta.to.shared.u64 t, %1; cvt.u32.u64 %0, t; }" : "=r"(a) : "l"(p));
    return a;
}
#define CP16(dst, src) asm volatile("cp.async.cg.shared.global [%0], [%1], 16;" :: "r"(dst), "l"(src) : "memory")
#define CPCOMMIT()     asm volatile("cp.async.commit_group;" ::: "memory")
#define CPWAIT1()      asm volatile("cp.async.wait_group 1;" ::: "memory")
#define CPWAIT0()      asm volatile("cp.async.wait_group 0;" ::: "memory")

// ---------------------------------------------------------------------------
// QKV projection (128 thr, grid (32, B)). q,k scalar f32 (+norms);
// V projection on tensor cores (f16 HMMA, non-volatile: scheduler-free).
// ---------------------------------------------------------------------------
#define XS 72

__global__ __launch_bounds__(128) void qkv_kernel(
    const float* __restrict__ x,
    const float* __restrict__ wq, const float* __restrict__ bq,
    const float* __restrict__ wk, const float* __restrict__ bk,
    const float* __restrict__ wv, const float* __restrict__ bv)
{
    __shared__ float swq[DQ * CCH], swk[DQ * CCH];
    __shared__ float sbq[DQ], sbk[DQ], sbv[CCH];
    __shared__ float swmax[4];
    __shared__ __align__(16) __half wv16[CCH][XS];
    __shared__ __align__(16) __half xs[128][XS];

    const int tid = threadIdx.x;
    const int w    = tid >> 5;
    const int lane = tid & 31;
    const int g    = lane >> 2;
    const int c    = lane & 3;
    const int b = blockIdx.y;
    const int n0 = blockIdx.x * 128;

    for (int i = tid; i < DQ * CCH; i += 128) { swq[i] = wq[i]; swk[i] = wk[i]; }
    for (int i = tid; i < CCH * CCH; i += 128) {
        wv16[i >> 6][i & 63] = __float2half_rn(wv[i]);
    }
    if (tid < DQ) { sbq[tid] = bq[tid]; sbk[tid] = bk[tid]; }
    if (tid < CCH) sbv[tid] = bv[tid];

    const int n = n0 + tid;
    float xv[CCH];
    const float* xb = x + ((size_t)b * CCH) * NPIX + n;
    #pragma unroll
    for (int ch = 0; ch < CCH; ch++) xv[ch] = xb[(size_t)ch * NPIX];

    #pragma unroll
    for (int ch = 0; ch < CCH; ch += 2) {
        __half2 h = __floats2half2_rn(xv[ch], xv[ch + 1]);
        *(__half2*)&xs[tid][ch] = h;
    }
    __syncthreads();

    float qv[DQ], kv[DQ];
    #pragma unroll
    for (int d = 0; d < DQ; d++) {
        float aq = sbq[d], ak = sbk[d];
        #pragma unroll
        for (int ch = 0; ch < CCH; ch++) {
            aq = fmaf(swq[d * CCH + ch], xv[ch], aq);
            ak = fmaf(swk[d * CCH + ch], xv[ch], ak);
        }
        qv[d] = aq; kv[d] = ak;
    }
    {
        __half2* qo = (__half2*)&g_q16[((size_t)b * NPIX + n) * DQ];
        __half2* ko = (__half2*)&g_k16[((size_t)b * NPIX + n) * DQ];
        #pragma unroll
        for (int d = 0; d < 4; d++) {
            qo[d] = __floats2half2_rn(qv[2*d] * L2E, qv[2*d+1] * L2E);
            ko[d] = __floats2half2_rn(kv[2*d], kv[2*d+1]);
        }
    }
    {
        float nq2 = 0.f, nk2 = 0.f;
        #pragma unroll
        for (int d = 0; d < DQ; d++) {
            nq2 = fmaf(qv[d], qv[d], nq2);
            nk2 = fmaf(kv[d], kv[d], nk2);
        }
        g_qn[b * NPIX + n] = sqrtf(nq2);
        float nk = sqrtf(nk2);
        #pragma unroll
        for (int off = 16; off > 0; off >>= 1)
            nk = fmaxf(nk, __shfl_xor_sync(0xFFFFFFFFu, nk, off));
        if (lane == 0) swmax[w] = nk;
    }
    __syncthreads();
    if (tid == 0)
        g_kmax_part[b * 32 + blockIdx.x] =
            fmaxf(fmaxf(swmax[0], swmax[1]), fmaxf(swmax[2], swmax[3]));

    uint32_t bf[4][4][2];
    #pragma unroll
    for (int ni = 0; ni < 4; ni++) {
        #pragma unroll
        for (int kp = 0; kp < 2; kp++) {
            const int row = w * 32 + ni * 8 + (lane & 7);
            const int col = kp * 32 + (lane >> 3) * 8;
            uint32_t addr = s2u(&xs[row][col]);
            uint32_t r0, r1, r2, r3;
            asm volatile("ldmatrix.sync.aligned.m8n8.x4.shared.b16 {%0,%1,%2,%3}, [%4];"
                : "=r"(r0), "=r"(r1), "=r"(r2), "=r"(r3) : "r"(addr));
            bf[ni][2*kp][0]   = r0; bf[ni][2*kp][1]   = r1;
            bf[ni][2*kp+1][0] = r2; bf[ni][2*kp+1][1] = r3;
        }
    }
    #pragma unroll
    for (int mi = 0; mi < 4; mi++) {
        uint32_t af[4][4];
        #pragma unroll
        for (int ki = 0; ki < 4; ki++) {
            const int row = mi * 16 + (((lane >> 3) & 1) << 3) + (lane & 7);
            const int col = ki * 16 + ((lane >> 4) << 3);
            uint32_t addr = s2u(&wv16[row][col]);
            asm volatile("ldmatrix.sync.aligned.m8n8.x4.shared.b16 {%0,%1,%2,%3}, [%4];"
                : "=r"(af[ki][0]), "=r"(af[ki][1]), "=r"(af[ki][2]), "=r"(af[ki][3]) : "r"(addr));
        }
        __half2 c0h = __float2half2_rn(sbv[mi * 16 + g]);
        __half2 c1h = __float2half2_rn(sbv[mi * 16 + 8 + g]);
        const uint32_t c0 = *(uint32_t*)&c0h, c1 = *(uint32_t*)&c1h;
        #pragma unroll
        for (int ni = 0; ni < 4; ni++) {
            uint32_t d0 = c0, d1 = c1;
            #pragma unroll
            for (int ki = 0; ki < 4; ki++) {
                asm("mma.sync.aligned.m16n8k16.row.col.f16.f16.f16.f16 "
                    "{%0,%1},{%2,%3,%4,%5},{%6,%7},{%0,%1};"
                    : "+r"(d0), "+r"(d1)
                    : "r"(af[ki][0]), "r"(af[ki][1]), "r"(af[ki][2]), "r"(af[ki][3]),
                      "r"(bf[ni][ki][0]), "r"(bf[ni][ki][1]));
            }
            const int px = n0 + w * 32 + ni * 8 + 2 * c;
            const int r0 = mi * 16 + g;
            *(uint32_t*)&g_v16[((size_t)(b * CCH + r0))     * NPIX + px] = d0;
            *(uint32_t*)&g_v16[((size_t)(b * CCH + r0 + 8)) * NPIX + px] = d1;
        }
    }
}

// ---------------------------------------------------------------------------
// Flash attention, 256 thr / 8 warps, warp owns 16 m-rows, TN=256.
// All MMAs NON-volatile: ptxas may interleave kc iterations to hide the
// S->ex2->PV latency chain. ldmatrix stays volatile (smem ordering).
// ---------------------------------------------------------------------------
#define VSTRIDE 264
#define STAGE(t, buf) do { \
    const __half* _ks = g_k16 + ((size_t)b * NPIX + (t) * TN + tid) * DQ; \
    CP16(s2u(&sK[buf][tid][0]), _ks); \
    _Pragma("unroll") \
    for (int _i = 0; _i < 8; _i++) { \
        int _l = _i * 256 + tid, _row = _l >> 5, _seg = _l & 31; \
        const __half* _vs = g_v16 + ((size_t)(b * CCH + _row)) * NPIX + (t) * TN + _seg * 8; \
        CP16(s2u(&sV[buf][_row][_seg * 8]), _vs); \
    } \
} while (0)

__global__ __launch_bounds__(256, 2) void attn_kernel(
    const float* __restrict__ x,
    const float* __restrict__ gamma,
    float* __restrict__ out)
{
    __shared__ __align__(16) __half sK[2][TN][24];
    __shared__ __align__(16) __half sV[2][CCH][VSTRIDE];

    const int tid  = threadIdx.x;
    const int w    = tid >> 5;
    const int lane = tid & 31;
    const int g    = lane >> 2;
    const int c    = lane & 3;
    const int b    = blockIdx.y;
    const int m0   = blockIdx.x * TM + w * 16;

    float kmax = g_kmax_part[b * 32];
    #pragma unroll
    for (int i = 1; i < 32; i++) kmax = fmaxf(kmax, g_kmax_part[b * 32 + i]);

    uint32_t qa0, qa1;
    uint32_t nshC0, nshC1;
    {
        const int rA = m0 + g, rB = rA + 8;
        qa0 = *(const uint32_t*)&g_q16[((size_t)b * NPIX + rA) * DQ + 2 * c];
        qa1 = *(const uint32_t*)&g_q16[((size_t)b * NPIX + rB) * DQ + 2 * c];
        float nA = -g_qn[b * NPIX + rA] * kmax * L2E;
        float nB = -g_qn[b * NPIX + rB] * kmax * L2E;
        __half2 hA = __floats2half2_rn(nA, nA);
        __half2 hB = __floats2half2_rn(nB, nB);
        nshC0 = *(uint32_t*)&hA;
        nshC1 = *(uint32_t*)&hB;
    }

    float acc32[8][4];
    #pragma unroll
    for (int jc = 0; jc < 8; jc++)
        #pragma unroll
        for (int r = 0; r < 4; r++) acc32[jc][r] = 0.f;
    float ls32[2] = {0.f, 0.f};

    const uint32_t vb0 = s2u(&sV[0][((lane >> 4) << 3) + (lane & 7)][((lane >> 3) & 1) * 8]);

    STAGE(0, 0); CPCOMMIT();

    #pragma unroll 1
    for (int t = 0; t < NT; t++) {
        if (t + 1 < NT) { STAGE(t + 1, (t + 1) & 1); CPCOMMIT(); CPWAIT1(); }
        else            { CPWAIT0(); }
        __syncthreads();
        const __half (*K)[24] = sK[t & 1];
        const uint32_t vbase = vb0 + (uint32_t)((t & 1) * CCH * VSTRIDE * 2);

        uint32_t a16[9][2];
        #pragma unroll
        for (int jc = 0; jc < 9; jc++) { a16[jc][0] = 0u; a16[jc][1] = 0u; }

        #pragma unroll
        for (int kc = 0; kc < 16; kc++) {
            const uint32_t kb0 = *(const uint32_t*)&K[kc * 16 + g][2 * c];
            const uint32_t kb1 = *(const uint32_t*)&K[kc * 16 + 8 + g][2 * c];
            uint32_t pf[4];
            {
                uint32_t d0, d1, d2, d3;
                asm("mma.sync.aligned.m16n8k8.row.col.f16.f16.f16.f16 "
                    "{%0,%1},{%2,%3},{%4},{%5,%6};"
                    : "=r"(d0), "=r"(d1)
                    : "r"(qa0), "r"(qa1), "r"(kb0), "r"(nshC0), "r"(nshC1));
                asm("mma.sync.aligned.m16n8k8.row.col.f16.f16.f16.f16 "
                    "{%0,%1},{%2,%3},{%4},{%5,%6};"
                    : "=r"(d2), "=r"(d3)
                    : "r"(qa0), "r"(qa1), "r"(kb1), "r"(nshC0), "r"(nshC1));
                asm("ex2.approx.f16x2 %0, %1;" : "=r"(pf[0]) : "r"(d0));
                asm("ex2.approx.f16x2 %0, %1;" : "=r"(pf[1]) : "r"(d1));
                asm("ex2.approx.f16x2 %0, %1;" : "=r"(pf[2]) : "r"(d2));
                asm("ex2.approx.f16x2 %0, %1;" : "=r"(pf[3]) : "r"(d3));
            }
            #pragma unroll
            for (int jp = 0; jp < 4; jp++) {
                uint32_t b00, b01, b10, b11;
                const uint32_t va = vbase + (uint32_t)(jp * 16 * VSTRIDE * 2 + kc * 32);
                asm volatile("ldmatrix.sync.aligned.m8n8.x4.shared.b16 {%0,%1,%2,%3}, [%4];"
                    : "=r"(b00), "=r"(b01), "=r"(b10), "=r"(b11) : "r"(va));
                asm("mma.sync.aligned.m16n8k16.row.col.f16.f16.f16.f16 "
                    "{%0,%1},{%2,%3,%4,%5},{%6,%7},{%0,%1};"
                    : "+r"(a16[2*jp][0]), "+r"(a16[2*jp][1])
                    : "r"(pf[0]), "r"(pf[1]), "r"(pf[2]), "r"(pf[3]),
                      "r"(b00), "r"(b01));
                asm("mma.sync.aligned.m16n8k16.row.col.f16.f16.f16.f16 "
                    "{%0,%1},{%2,%3,%4,%5},{%6,%7},{%0,%1};"
                    : "+r"(a16[2*jp+1][0]), "+r"(a16[2*jp+1][1])
                    : "r"(pf[0]), "r"(pf[1]), "r"(pf[2]), "r"(pf[3]),
                      "r"(b10), "r"(b11));
            }
            {
                const uint32_t ones = 0x3C003C00u;
                asm("mma.sync.aligned.m16n8k16.row.col.f16.f16.f16.f16 "
                    "{%0,%1},{%2,%3,%4,%5},{%6,%7},{%0,%1};"
                    : "+r"(a16[8][0]), "+r"(a16[8][1])
                    : "r"(pf[0]), "r"(pf[1]), "r"(pf[2]), "r"(pf[3]),
                      "r"(ones), "r"(ones));
            }
        }
        #pragma unroll
        for (int jc = 0; jc < 8; jc++) {
            float2 f0 = __half22float2(*(__half2*)&a16[jc][0]);
            float2 f1 = __half22float2(*(__half2*)&a16[jc][1]);
            acc32[jc][0] += f0.x; acc32[jc][1] += f0.y;
            acc32[jc][2] += f1.x; acc32[jc][3] += f1.y;
        }
        ls32[0] += __half2float(*(__half*)&a16[8][0]);
        ls32[1] += __half2float(*(__half*)&a16[8][1]);
        __syncthreads();
    }

    const float gm = gamma[0];
    const float iA = 1.f / ls32[0], iB = 1.f / ls32[1];
    const int rA = m0 + g, rB = rA + 8;
    const float* xb = x   + (size_t)b * CCH * NPIX;
    float*       ob = out + (size_t)b * CCH * NPIX;
    #pragma unroll
    for (int jc = 0; jc < 8; jc++) {
        const int ch0 = jc * 8 + 2 * c, ch1 = ch0 + 1;
        ob[(size_t)ch0 * NPIX + rA] = fmaf(gm, acc32[jc][0] * iA, xb[(size_t)ch0 * NPIX + rA]);
        ob[(size_t)ch1 * NPIX + rA] = fmaf(gm, acc32[jc][1] * iA, xb[(size_t)ch1 * NPIX + rA]);
        ob[(size_t)ch0 * NPIX + rB] = fmaf(gm, acc32[jc][2] * iB, xb[(size_t)ch0 * NPIX + rB]);
        ob[(size_t)ch1 * NPIX + rB] = fmaf(gm, acc32[jc][3] * iB, xb[(size_t)ch1 * NPIX + rB]);
    }
}

// ---------------------------------------------------------------------------
extern "C" void kernel_launch(void* const* d_in, const int* in_sizes, int n_in,
                              void* d_out, int out_size)
{
    const float* x     = (const float*)d_in[0];
    const float* wq    = (const float*)d_in[1];
    const float* bq    = (const float*)d_in[2];
    const float* wk    = (const float*)d_in[3];
    const float* bk    = (const float*)d_in[4];
    const float* wv    = (const float*)d_in[5];
    const float* bv    = (const float*)d_in[6];
    const float* gamma = (const float*)d_in[7];
    float* out = (float*)d_out;

    dim3 g1(NPIX / 128, BATCH);
    qkv_kernel<<<g1, 128>>>(x, wq, bq, wk, bk, wv, bv);
    dim3 g2(NPIX / TM, BATCH);
    attn_kernel<<<g2, 256>>>(x, gamma, out);
}

// round 17
// speedup vs baseline: 1.3818x; 1.0024x over previous
#include <cuda_runtime.h>
#include <cuda_fp16.h>
#include <cstdint>

#define BATCH 8
#define CCH   64
#define DQ    8
#define NPIX  4096
#define TM    128
#define TN    256
#define NT    (NPIX / TN)
#define L2E   1.4426950408889634f

__device__ __half g_q16[BATCH * NPIX * DQ];                 // pre-scaled by log2(e)
__device__ __half g_k16[BATCH * NPIX * DQ];
__device__ float  g_qn[BATCH * NPIX];
__device__ __half g_v16[(size_t)BATCH * CCH * NPIX];        // [b][c][n]
__device__ float  g_kmax_part[BATCH * 32];

__device__ __forceinline__ uint32_t s2u(const void* p) {
    uint32_t a;
    asm("{ .reg .u64 t; cvta.to.shared.u64 t, %1; cvt.u32.u64 %0, t; }" : "=r"(a) : "l"(p));
    return a;
}
#define CP16(dst, src) asm volatile("cp.async.cg.shared.global [%0], [%1], 16;" :: "r"(dst), "l"(src) : "memory")
#define CPCOMMIT()     asm volatile("cp.async.commit_group;" ::: "memory")
#define CPWAIT1()      asm volatile("cp.async.wait_group 1;" ::: "memory")
#define CPWAIT0()      asm volatile("cp.async.wait_group 0;" ::: "memory")

// ---------------------------------------------------------------------------
// QKV projection (128 thr, grid (32, B)). q,k scalar f32 (+norms);
// V projection on tensor cores (f16 HMMA). (R13, unchanged)
// ---------------------------------------------------------------------------
#define XS 72

__global__ __launch_bounds__(128) void qkv_kernel(
    const float* __restrict__ x,
    const float* __restrict__ wq, const float* __restrict__ bq,
    const float* __restrict__ wk, const float* __restrict__ bk,
    const float* __restrict__ wv, const float* __restrict__ bv)
{
    __shared__ float swq[DQ * CCH], swk[DQ * CCH];
    __shared__ float sbq[DQ], sbk[DQ], sbv[CCH];
    __shared__ float swmax[4];
    __shared__ __align__(16) __half wv16[CCH][XS];
    __shared__ __align__(16) __half xs[128][XS];

    const int tid = threadIdx.x;
    const int w    = tid >> 5;
    const int lane = tid & 31;
    const int g    = lane >> 2;
    const int c    = lane & 3;
    const int b = blockIdx.y;
    const int n0 = blockIdx.x * 128;

    for (int i = tid; i < DQ * CCH; i += 128) { swq[i] = wq[i]; swk[i] = wk[i]; }
    for (int i = tid; i < CCH * CCH; i += 128) {
        wv16[i >> 6][i & 63] = __float2half_rn(wv[i]);
    }
    if (tid < DQ) { sbq[tid] = bq[tid]; sbk[tid] = bk[tid]; }
    if (tid < CCH) sbv[tid] = bv[tid];

    const int n = n0 + tid;
    float xv[CCH];
    const float* xb = x + ((size_t)b * CCH) * NPIX + n;
    #pragma unroll
    for (int ch = 0; ch < CCH; ch++) xv[ch] = xb[(size_t)ch * NPIX];

    #pragma unroll
    for (int ch = 0; ch < CCH; ch += 2) {
        __half2 h = __floats2half2_rn(xv[ch], xv[ch + 1]);
        *(__half2*)&xs[tid][ch] = h;
    }
    __syncthreads();

    float qv[DQ], kv[DQ];
    #pragma unroll
    for (int d = 0; d < DQ; d++) {
        float aq = sbq[d], ak = sbk[d];
        #pragma unroll
        for (int ch = 0; ch < CCH; ch++) {
            aq = fmaf(swq[d * CCH + ch], xv[ch], aq);
            ak = fmaf(swk[d * CCH + ch], xv[ch], ak);
        }
        qv[d] = aq; kv[d] = ak;
    }
    {
        __half2* qo = (__half2*)&g_q16[((size_t)b * NPIX + n) * DQ];
        __half2* ko = (__half2*)&g_k16[((size_t)b * NPIX + n) * DQ];
        #pragma unroll
        for (int d = 0; d < 4; d++) {
            qo[d] = __floats2half2_rn(qv[2*d] * L2E, qv[2*d+1] * L2E);
            ko[d] = __floats2half2_rn(kv[2*d], kv[2*d+1]);
        }
    }
    {
        float nq2 = 0.f, nk2 = 0.f;
        #pragma unroll
        for (int d = 0; d < DQ; d++) {
            nq2 = fmaf(qv[d], qv[d], nq2);
            nk2 = fmaf(kv[d], kv[d], nk2);
        }
        g_qn[b * NPIX + n] = sqrtf(nq2);
        float nk = sqrtf(nk2);
        #pragma unroll
        for (int off = 16; off > 0; off >>= 1)
            nk = fmaxf(nk, __shfl_xor_sync(0xFFFFFFFFu, nk, off));
        if (lane == 0) swmax[w] = nk;
    }
    __syncthreads();
    if (tid == 0)
        g_kmax_part[b * 32 + blockIdx.x] =
            fmaxf(fmaxf(swmax[0], swmax[1]), fmaxf(swmax[2], swmax[3]));

    uint32_t bf[4][4][2];
    #pragma unroll
    for (int ni = 0; ni < 4; ni++) {
        #pragma unroll
        for (int kp = 0; kp < 2; kp++) {
            const int row = w * 32 + ni * 8 + (lane & 7);
            const int col = kp * 32 + (lane >> 3) * 8;
            uint32_t addr = s2u(&xs[row][col]);
            uint32_t r0, r1, r2, r3;
            asm volatile("ldmatrix.sync.aligned.m8n8.x4.shared.b16 {%0,%1,%2,%3}, [%4];"
                : "=r"(r0), "=r"(r1), "=r"(r2), "=r"(r3) : "r"(addr));
            bf[ni][2*kp][0]   = r0; bf[ni][2*kp][1]   = r1;
            bf[ni][2*kp+1][0] = r2; bf[ni][2*kp+1][1] = r3;
        }
    }
    #pragma unroll
    for (int mi = 0; mi < 4; mi++) {
        uint32_t af[4][4];
        #pragma unroll
        for (int ki = 0; ki < 4; ki++) {
            const int row = mi * 16 + (((lane >> 3) & 1) << 3) + (lane & 7);
            const int col = ki * 16 + ((lane >> 4) << 3);
            uint32_t addr = s2u(&wv16[row][col]);
            asm volatile("ldmatrix.sync.aligned.m8n8.x4.shared.b16 {%0,%1,%2,%3}, [%4];"
                : "=r"(af[ki][0]), "=r"(af[ki][1]), "=r"(af[ki][2]), "=r"(af[ki][3]) : "r"(addr));
        }
        __half2 c0h = __float2half2_rn(sbv[mi * 16 + g]);
        __half2 c1h = __float2half2_rn(sbv[mi * 16 + 8 + g]);
        const uint32_t c0 = *(uint32_t*)&c0h, c1 = *(uint32_t*)&c1h;
        #pragma unroll
        for (int ni = 0; ni < 4; ni++) {
            uint32_t d0 = c0, d1 = c1;
            #pragma unroll
            for (int ki = 0; ki < 4; ki++) {
                asm("mma.sync.aligned.m16n8k16.row.col.f16.f16.f16.f16 "
                    "{%0,%1},{%2,%3,%4,%5},{%6,%7},{%0,%1};"
                    : "+r"(d0), "+r"(d1)
                    : "r"(af[ki][0]), "r"(af[ki][1]), "r"(af[ki][2]), "r"(af[ki][3]),
                      "r"(bf[ni][ki][0]), "r"(bf[ni][ki][1]));
            }
            const int px = n0 + w * 32 + ni * 8 + 2 * c;
            const int r0 = mi * 16 + g;
            *(uint32_t*)&g_v16[((size_t)(b * CCH + r0))     * NPIX + px] = d0;
            *(uint32_t*)&g_v16[((size_t)(b * CCH + r0 + 8)) * NPIX + px] = d1;
        }
    }
}

// ---------------------------------------------------------------------------
// Flash attention, 128 thr / 4 warps, warp owns 32 m-rows (mt=2), TN=256.
// V ldmatrix shared across mt -> half the L1 traffic per MMA vs mt=1.
// f16-acc window + f32 promotion; lsum via f16 ones-MMA. Grid (32, 8).
// ---------------------------------------------------------------------------
#define VSTRIDE 264
#define STAGE(t, buf) do { \
    const __half* _ks = g_k16 + ((size_t)b * NPIX + (t) * TN + tid) * DQ; \
    CP16(s2u(&sK[buf][tid][0]), _ks); \
    CP16(s2u(&sK[buf][tid + 128][0]), _ks + 128 * DQ); \
    _Pragma("unroll") \
    for (int _i = 0; _i < 16; _i++) { \
        int _l = _i * 128 + tid, _row = _l >> 5, _seg = _l & 31; \
        const __half* _vs = g_v16 + ((size_t)(b * CCH + _row)) * NPIX + (t) * TN + _seg * 8; \
        CP16(s2u(&sV[buf][_row][_seg * 8]), _vs); \
    } \
} while (0)

__global__ __launch_bounds__(128, 2) void attn_kernel(
    const float* __restrict__ x,
    const float* __restrict__ gamma,
    float* __restrict__ out)
{
    __shared__ __align__(16) __half sK[2][TN][24];
    __shared__ __align__(16) __half sV[2][CCH][VSTRIDE];

    const int tid  = threadIdx.x;
    const int w    = tid >> 5;
    const int lane = tid & 31;
    const int g    = lane >> 2;
    const int c    = lane & 3;
    const int b    = blockIdx.y;
    const int m0   = blockIdx.x * TM + w * 32;

    float kmax = g_kmax_part[b * 32];
    #pragma unroll
    for (int i = 1; i < 32; i++) kmax = fmaxf(kmax, g_kmax_part[b * 32 + i]);

    uint32_t qa0[2], qa1[2];
    uint32_t nshC[2][2];
    #pragma unroll
    for (int mt = 0; mt < 2; mt++) {
        const int rA = m0 + mt * 16 + g, rB = rA + 8;
        qa0[mt] = *(const uint32_t*)&g_q16[((size_t)b * NPIX + rA) * DQ + 2 * c];
        qa1[mt] = *(const uint32_t*)&g_q16[((size_t)b * NPIX + rB) * DQ + 2 * c];
        float nA = -g_qn[b * NPIX + rA] * kmax * L2E;
        float nB = -g_qn[b * NPIX + rB] * kmax * L2E;
        __half2 hA = __floats2half2_rn(nA, nA);
        __half2 hB = __floats2half2_rn(nB, nB);
        nshC[mt][0] = *(uint32_t*)&hA;
        nshC[mt][1] = *(uint32_t*)&hB;
    }

    float acc32[2][8][4];
    #pragma unroll
    for (int mt = 0; mt < 2; mt++)
        #pragma unroll
        for (int jc = 0; jc < 8; jc++)
            #pragma unroll
            for (int r = 0; r < 4; r++) acc32[mt][jc][r] = 0.f;
    float ls32[4] = {0.f, 0.f, 0.f, 0.f};

    const uint32_t vb0 = s2u(&sV[0][((lane >> 4) << 3) + (lane & 7)][((lane >> 3) & 1) * 8]);

    STAGE(0, 0); CPCOMMIT();

    #pragma unroll 1
    for (int t = 0; t < NT; t++) {
        if (t + 1 < NT) { STAGE(t + 1, (t + 1) & 1); CPCOMMIT(); CPWAIT1(); }
        else            { CPWAIT0(); }
        __syncthreads();
        const __half (*K)[24] = sK[t & 1];
        const uint32_t vbase = vb0 + (uint32_t)((t & 1) * CCH * VSTRIDE * 2);

        uint32_t a16[2][9][2];
        #pragma unroll
        for (int mt = 0; mt < 2; mt++)
            #pragma unroll
            for (int jc = 0; jc < 9; jc++) { a16[mt][jc][0] = 0u; a16[mt][jc][1] = 0u; }

        #pragma unroll
        for (int kc = 0; kc < 16; kc++) {
            const uint32_t kb0 = *(const uint32_t*)&K[kc * 16 + g][2 * c];
            const uint32_t kb1 = *(const uint32_t*)&K[kc * 16 + 8 + g][2 * c];
            uint32_t pf[2][4];
            #pragma unroll
            for (int mt = 0; mt < 2; mt++) {
                uint32_t d0, d1, d2, d3;
                asm("mma.sync.aligned.m16n8k8.row.col.f16.f16.f16.f16 "
                    "{%0,%1},{%2,%3},{%4},{%5,%6};"
                    : "=r"(d0), "=r"(d1)
                    : "r"(qa0[mt]), "r"(qa1[mt]), "r"(kb0), "r"(nshC[mt][0]), "r"(nshC[mt][1]));
                asm("mma.sync.aligned.m16n8k8.row.col.f16.f16.f16.f16 "
                    "{%0,%1},{%2,%3},{%4},{%5,%6};"
                    : "=r"(d2), "=r"(d3)
                    : "r"(qa0[mt]), "r"(qa1[mt]), "r"(kb1), "r"(nshC[mt][0]), "r"(nshC[mt][1]));
                asm("ex2.approx.f16x2 %0, %1;" : "=r"(pf[mt][0]) : "r"(d0));
                asm("ex2.approx.f16x2 %0, %1;" : "=r"(pf[mt][1]) : "r"(d1));
                asm("ex2.approx.f16x2 %0, %1;" : "=r"(pf[mt][2]) : "r"(d2));
                asm("ex2.approx.f16x2 %0, %1;" : "=r"(pf[mt][3]) : "r"(d3));
            }
            #pragma unroll
            for (int jp = 0; jp < 4; jp++) {
                uint32_t b00, b01, b10, b11;
                const uint32_t va = vbase + (uint32_t)(jp * 16 * VSTRIDE * 2 + kc * 32);
                asm volatile("ldmatrix.sync.aligned.m8n8.x4.shared.b16 {%0,%1,%2,%3}, [%4];"
                    : "=r"(b00), "=r"(b01), "=r"(b10), "=r"(b11) : "r"(va));
                #pragma unroll
                for (int mt = 0; mt < 2; mt++) {
                    asm("mma.sync.aligned.m16n8k16.row.col.f16.f16.f16.f16 "
                        "{%0,%1},{%2,%3,%4,%5},{%6,%7},{%0,%1};"
                        : "+r"(a16[mt][2*jp][0]), "+r"(a16[mt][2*jp][1])
                        : "r"(pf[mt][0]), "r"(pf[mt][1]), "r"(pf[mt][2]), "r"(pf[mt][3]),
                          "r"(b00), "r"(b01));
                    asm("mma.sync.aligned.m16n8k16.row.col.f16.f16.f16.f16 "
                        "{%0,%1},{%2,%3,%4,%5},{%6,%7},{%0,%1};"
                        : "+r"(a16[mt][2*jp+1][0]), "+r"(a16[mt][2*jp+1][1])
                        : "r"(pf[mt][0]), "r"(pf[mt][1]), "r"(pf[mt][2]), "r"(pf[mt][3]),
                          "r"(b10), "r"(b11));
                }
            }
            {
                const uint32_t ones = 0x3C003C00u;
                #pragma unroll
                for (int mt = 0; mt < 2; mt++) {
                    asm("mma.sync.aligned.m16n8k16.row.col.f16.f16.f16.f16 "
                        "{%0,%1},{%2,%3,%4,%5},{%6,%7},{%0,%1};"
                        : "+r"(a16[mt][8][0]), "+r"(a16[mt][8][1])
                        : "r"(pf[mt][0]), "r"(pf[mt][1]), "r"(pf[mt][2]), "r"(pf[mt][3]),
                          "r"(ones), "r"(ones));
                }
            }
        }
        #pragma unroll
        for (int mt = 0; mt < 2; mt++) {
            #pragma unroll
            for (int jc = 0; jc < 8; jc++) {
                float2 f0 = __half22float2(*(__half2*)&a16[mt][jc][0]);
                float2 f1 = __half22float2(*(__half2*)&a16[mt][jc][1]);
                acc32[mt][jc][0] += f0.x; acc32[mt][jc][1] += f0.y;
                acc32[mt][jc][2] += f1.x; acc32[mt][jc][3] += f1.y;
            }
            ls32[2*mt]   += __half2float(*(__half*)&a16[mt][8][0]);
            ls32[2*mt+1] += __half2float(*(__half*)&a16[mt][8][1]);
        }
        __syncthreads();
    }

    const float gm = gamma[0];
    const float* xb = x   + (size_t)b * CCH * NPIX;
    float*       ob = out + (size_t)b * CCH * NPIX;
    #pragma unroll
    for (int mt = 0; mt < 2; mt++) {
        const float iA = 1.f / ls32[2*mt], iB = 1.f / ls32[2*mt+1];
        const int rA = m0 + mt * 16 + g, rB = rA + 8;
        #pragma unroll
        for (int jc = 0; jc < 8; jc++) {
            const int ch0 = jc * 8 + 2 * c, ch1 = ch0 + 1;
            ob[(size_t)ch0 * NPIX + rA] = fmaf(gm, acc32[mt][jc][0] * iA, xb[(size_t)ch0 * NPIX + rA]);
            ob[(size_t)ch1 * NPIX + rA] = fmaf(gm, acc32[mt][jc][1] * iA, xb[(size_t)ch1 * NPIX + rA]);
            ob[(size_t)ch0 * NPIX + rB] = fmaf(gm, acc32[mt][jc][2] * iB, xb[(size_t)ch0 * NPIX + rB]);
            ob[(size_t)ch1 * NPIX + rB] = fmaf(gm, acc32[mt][jc][3] * iB, xb[(size_t)ch1 * NPIX + rB]);
        }
    }
}

// ---------------------------------------------------------------------------
extern "C" void kernel_launch(void* const* d_in, const int* in_sizes, int n_in,
                              void* d_out, int out_size)
{
    const float* x     = (const float*)d_in[0];
    const float* wq    = (const float*)d_in[1];
    const float* bq    = (const float*)d_in[2];
    const float* wk    = (const float*)d_in[3];
    const float* bk    = (const float*)d_in[4];
    const float* wv    = (const float*)d_in[5];
    const float* bv    = (const float*)d_in[6];
    const float* gamma = (const float*)d_in[7];
    float* out = (float*)d_out;

    dim3 g1(NPIX / 128, BATCH);
    qkv_kernel<<<g1, 128>>>(x, wq, bq, wk, bk, wv, bv);
    dim3 g2(NPIX / TM, BATCH);
    attn_kernel<<<g2, 128>>>(x, gamma, out);
}